// round 16
// baseline (speedup 1.0000x reference)
#include <cuda_runtime.h>
#include <cstdint>

#define BDIM   8
#define PDIM   120000
#define NCLS   5
#define CFG    4
#define NPAIR  (BDIM * CFG)
#define TOPK   1000
#define NBINS  16384
#define CAP    4096
#define NWORDS 16           // u64 words per mask row
#define MCHUNK 16           // mask-build CTAs per pair
#define MASK_BYTES (TOPK * NWORDS * 8)   // 128000 bytes per pair

typedef unsigned long long u64;
typedef unsigned int u32;

// ---- static device scratch ----
__device__ float  g_scores[NPAIR * PDIM];
__device__ u64    g_mask[(size_t)NPAIR * TOPK * NWORDS];
__device__ float4 g_box[NPAIR * 1024];      // point form, zero-padded
__device__ float  g_area[NPAIR * 1024];
__device__ float4 g_cscand[NPAIR * 1024];   // center-size of candidates
__device__ float  g_score[NPAIR * 1024];
__device__ int    g_kv[NPAIR];

// =====================================================================
// Kernel 1: softmax scores ONLY (exact *_rn op order == XLA HLO).
// Box decode is deferred to select_kernel emit (candidates only) —
// removes 2 expf + loc/prior reads + 15MB g_cs write from the hot path.
// =====================================================================
__global__ void score_kernel(const float* __restrict__ conf) {
    int idx = blockIdx.x * blockDim.x + threadIdx.x;
    if (idx >= BDIM * PDIM) return;
    int b = idx / PDIM;
    int p = idx - b * PDIM;

    const float* cb = conf + (size_t)b * NCLS * PDIM + p;
    float c0 = cb[0], c1 = cb[PDIM], c2 = cb[2 * PDIM], c3 = cb[3 * PDIM], c4 = cb[4 * PDIM];
    float mx = fmaxf(fmaxf(fmaxf(fmaxf(c0, c1), c2), c3), c4);
    float e0 = expf(__fsub_rn(c0, mx));
    float e1 = expf(__fsub_rn(c1, mx));
    float e2 = expf(__fsub_rn(c2, mx));
    float e3 = expf(__fsub_rn(c3, mx));
    float e4 = expf(__fsub_rn(c4, mx));
    float ssum = __fadd_rn(__fadd_rn(__fadd_rn(__fadd_rn(e0, e1), e2), e3), e4);
    size_t sb = (size_t)b * CFG * PDIM + p;
    g_scores[sb]            = __fdiv_rn(e1, ssum);
    g_scores[sb + PDIM]     = __fdiv_rn(e2, ssum);
    g_scores[sb + 2 * PDIM] = __fdiv_rn(e3, ssum);
    g_scores[sb + 3 * PDIM] = __fdiv_rn(e4, ssum);
}

// =====================================================================
// Kernel 2: per-(image,class) exact top-K selection (32 CTAs).
// Shared-mem histogram (bank-spread atomics). Emit now also decodes
// the candidate boxes from loc/prior (exact *_rn order, == reference).
// =====================================================================
__global__ void __launch_bounds__(1024, 1)
select_kernel(const float* __restrict__ conf_th_p,
              const float* __restrict__ loc,
              const float* __restrict__ prior) {
    const int pair = blockIdx.x;
    const int b = pair >> 2;
    const int tid = threadIdx.x;
    const float conf_th = *conf_th_p;

    extern __shared__ char sm[];
    int* hist = (int*)sm;       // 16384 ints = 64 KB
    u64* keys = (u64*)sm;       // aliases hist after scan

    __shared__ int scanA[1024];
    __shared__ int s_T, s_cnt;

    const float* sc = g_scores + (size_t)pair * PDIM;

    // histogram
    for (int i = tid; i < NBINS; i += 1024) hist[i] = 0;
    __syncthreads();
    for (int p = tid; p < PDIM; p += 1024) {
        float s = sc[p];
        if (s >= conf_th) {
            int bin = (int)(s * 16384.0f);
            if (bin > NBINS - 1) bin = NBINS - 1;
            atomicAdd(&hist[bin], 1);
        }
    }
    __syncthreads();

    // suffix scan -> cutoff bin T (1000th-largest lives in bin T)
    int base = tid * 16;
    int ps = 0;
#pragma unroll
    for (int k = 0; k < 16; k++) ps += hist[base + k];
    scanA[tid] = ps;
    __syncthreads();
    for (int off = 1; off < 1024; off <<= 1) {
        int v = scanA[tid];
        if (tid + off < 1024) v += scanA[tid + off];
        __syncthreads();
        scanA[tid] = v;
        __syncthreads();
    }
    int total = scanA[0];
    if (tid == 0) { s_T = 0; s_cnt = 0; }
    __syncthreads();
    if (total >= TOPK) {
        int after = (tid < 1023) ? scanA[tid + 1] : 0;
        if (after < TOPK && after + ps >= TOPK) {
            int acc = after;
            for (int bb = 15; bb >= 0; bb--) {
                acc += hist[base + bb];
                if (acc >= TOPK) { s_T = base + bb; break; }
            }
        }
    }
    __syncthreads();
    int T = s_T;

    // gather candidates: key = score_bits<<32 | ~idx (desc == lax.top_k)
    for (int p = tid; p < PDIM; p += 1024) {
        float s = sc[p];
        if (s >= conf_th) {
            int bin = (int)(s * 16384.0f);
            if (bin > NBINS - 1) bin = NBINS - 1;
            if (bin >= T) {
                int pos = atomicAdd(&s_cnt, 1);
                if (pos < CAP)
                    keys[pos] = ((u64)__float_as_uint(s) << 32) | (u32)(~(u32)p);
            }
        }
    }
    __syncthreads();
    int M = s_cnt; if (M > CAP) M = CAP;
    int S = 1024;
    while (S < M) S <<= 1;          // 1024/2048/4096
    for (int i = M + tid; i < S; i += 1024) keys[i] = 0ull;
    __syncthreads();

    // bitonic sort, descending, S elements
    for (int k2 = 2; k2 <= S; k2 <<= 1) {
        for (int j = k2 >> 1; j > 0; j >>= 1) {
            for (int i = tid; i < S; i += 1024) {
                int ixj = i ^ j;
                if (ixj > i) {
                    u64 a = keys[i], c = keys[ixj];
                    bool up = ((i & k2) == 0);
                    bool sw = up ? (a < c) : (a > c);
                    if (sw) { keys[i] = c; keys[ixj] = a; }
                }
            }
            __syncthreads();
        }
    }

    int Kv = (M < TOPK) ? M : TOPK;

    // emit candidates (zero-padded to 1024), decoding boxes here
    int i = tid;
    if (i < 1024) {
        size_t o = (size_t)pair * 1024 + i;
        if (i < Kv) {
            u64 key = keys[i];
            int p = (int)(~(u32)key);
            float s = __uint_as_float((u32)(key >> 32));

            // SSD decode (exact *_rn op order == reference)
            float4 pr = reinterpret_cast<const float4*>(prior)[p];
            const float* lb = loc + (size_t)b * 4 * PDIM + p;
            float l0 = lb[0], l1 = lb[PDIM], l2 = lb[2 * PDIM], l3 = lb[3 * PDIM];
            float cx = __fadd_rn(pr.x, __fmul_rn(__fmul_rn(l0, 0.1f), pr.z));
            float cy = __fadd_rn(pr.y, __fmul_rn(__fmul_rn(l1, 0.1f), pr.w));
            float w  = __fmul_rn(pr.z, expf(__fmul_rn(l2, 0.2f)));
            float h  = __fmul_rn(pr.w, expf(__fmul_rn(l3, 0.2f)));

            float hw = __fmul_rn(w, 0.5f);
            float hh = __fmul_rn(h, 0.5f);
            float X1 = __fsub_rn(cx, hw);
            float Y1 = __fsub_rn(cy, hh);
            float X2 = __fadd_rn(cx, hw);
            float Y2 = __fadd_rn(cy, hh);
            g_box[o] = make_float4(X1, Y1, X2, Y2);
            g_area[o] = __fmul_rn(fmaxf(__fsub_rn(X2, X1), 0.0f),
                                  fmaxf(__fsub_rn(Y2, Y1), 0.0f));
            g_cscand[o] = make_float4(cx, cy, w, h);
            g_score[o] = s;
        } else {
            g_box[o] = make_float4(0.f, 0.f, 0.f, 0.f);
            g_area[o] = 0.f;
            g_cscand[o] = make_float4(0.f, 0.f, 0.f, 0.f);
            g_score[o] = 0.f;
        }
    }
    if (tid == 0) g_kv[pair] = Kv;
}

// =====================================================================
// Kernel 3: suppression bitmask, full chip. Division-free IoU decision
// with exact __fdiv_rn fallback in a +-2e-6 guard band (bit-exact).
// =====================================================================
__global__ void __launch_bounds__(512)
mask_kernel(const float* __restrict__ nms_th_p) {
    const int pair = blockIdx.x & (NPAIR - 1);
    const int chunk = blockIdx.x >> 5;
    const float th = *nms_th_p;

    __shared__ float4 sbox[1024];
    __shared__ float  sarea[1024];

    const int Kv = g_kv[pair];
    for (int i = threadIdx.x; i < 1024; i += 512) {
        sbox[i]  = g_box[(size_t)pair * 1024 + i];
        sarea[i] = g_area[(size_t)pair * 1024 + i];
    }
    __syncthreads();

    u64* mrow = g_mask + (size_t)pair * TOPK * NWORDS;
    const int NT = Kv * NWORDS;
    for (int t = chunk * 512 + threadIdx.x; t < NT; t += MCHUNK * 512) {
        int i = t >> 4;
        int w = t & (NWORDS - 1);
        u64 mword = 0ull;
        int j0 = w << 6;
        int jend = j0 + 64; if (jend > Kv) jend = Kv;
        int jstart = (j0 > i + 1) ? j0 : (i + 1);
        if (jstart < jend) {
            float4 bi = sbox[i];
            float ai = sarea[i];
            for (int j = jstart; j < jend; j++) {
                float4 bj = sbox[j];
                float iw = fmaxf(__fsub_rn(fminf(bi.z, bj.z), fmaxf(bi.x, bj.x)), 0.0f);
                float ih = fmaxf(__fsub_rn(fminf(bi.w, bj.w), fmaxf(bi.y, bj.y)), 0.0f);
                float inter = __fmul_rn(iw, ih);
                float uni = fmaxf(__fsub_rn(__fadd_rn(ai, sarea[j]), inter), 1e-12f);
                float bb = __fmul_rn(th, uni);
                bool sup;
                if (inter > __fmul_rn(bb, 1.000002f)) sup = true;
                else if (inter < __fmul_rn(bb, 0.999998f)) sup = false;
                else sup = (__fdiv_rn(inter, uni) > th);
                if (sup) mword |= (1ull << (j - j0));
            }
        }
        mrow[t] = mword;
    }
}

// =====================================================================
// Kernel 4: chunked greedy sweep on a SHARED-MEMORY-resident mask.
// The full 128KB per-pair mask is bulk-copied into dynamic smem, then
// every mask access is an LDS. Apply loops are fully unrolled and
// predicated (independent loads -> pipelined, no per-iter scoreboard
// stall). Diagonal rows staged in registers before the serial chain.
// Bit-identical to serial greedy NMS order.
// =====================================================================
__global__ void __launch_bounds__(256)
sweep_kernel(float* __restrict__ out) {
    extern __shared__ u32 sm32[];               // 32000 u32 = 128000 B
    const int pair = blockIdx.x;
    const int tid = threadIdx.x;
    __shared__ u32 s_keep[32];
    __shared__ int s_pref[32];

    const int Kv = g_kv[pair];
    float* outp = out + (size_t)pair * TOPK * 5;

    // bulk copy mask -> smem (coalesced uint4)
    {
        const uint4* src = (const uint4*)(g_mask + (size_t)pair * TOPK * NWORDS);
        uint4* dst = (uint4*)sm32;
        for (int i = tid; i < MASK_BYTES / 16; i += 256) dst[i] = src[i];
    }
    for (int i = tid; i < TOPK * 5; i += 256) outp[i] = 0.0f;
    __syncthreads();

    if (tid < 32) {
        const int lane = tid;
        int n = Kv - (lane << 5);
        u32 keepw = (n >= 32) ? 0xffffffffu : (n > 0 ? ((1u << n) - 1u) : 0u);
        const int NC = (Kv + 31) >> 5;
        for (int c = 0; c < NC; c++) {
            if (lane == c) {
                // stage diagonal rows in registers (independent LDS),
                // then run the serial bit chain on registers only
                u32 d[32];
#pragma unroll
                for (int k = 0; k < 32; k++) {
                    int i = (c << 5) + k;
                    d[k] = (i < Kv) ? sm32[(i << 5) + c] : 0u;
                }
                u32 live = keepw;
#pragma unroll
                for (int k = 0; k < 32; k++)
                    if ((live >> k) & 1u) live &= ~d[k];
                keepw = live;
            }
            u32 kcw = __shfl_sync(0xffffffffu, keepw, c);
            if (lane > c && kcw) {
                u32 acc = 0u;
#pragma unroll
                for (int k = 0; k < 32; k++)
                    if ((kcw >> k) & 1u) acc |= sm32[(((c << 5) + k) << 5) + lane];
                keepw &= ~acc;
            }
        }
        s_keep[lane] = keepw;
    }
    __syncthreads();
    if (tid == 0) {
        int acc = 0;
        for (int w = 0; w < 32; w++) { s_pref[w] = acc; acc += __popc(s_keep[w]); }
    }
    __syncthreads();

    for (int i = tid; i < Kv; i += 256) {
        u32 kw = s_keep[i >> 5];
        if ((kw >> (i & 31)) & 1u) {
            int pos = s_pref[i >> 5] + __popc(kw & ((1u << (i & 31)) - 1u));
            float4 cs = g_cscand[(size_t)pair * 1024 + i];
            float* rr = outp + pos * 5;
            rr[0] = g_score[(size_t)pair * 1024 + i];
            rr[1] = cs.x; rr[2] = cs.y; rr[3] = cs.z; rr[4] = cs.w;
        }
    }
}

extern "C" void kernel_launch(void* const* d_in, const int* in_sizes, int n_in,
                              void* d_out, int out_size) {
    const float* loc   = (const float*)d_in[0];
    const float* conf  = (const float*)d_in[1];
    const float* prior = (const float*)d_in[2];
    const float* cth   = (const float*)d_in[3];
    const float* nth   = (const float*)d_in[4];
    float* out = (float*)d_out;

    cudaFuncSetAttribute(select_kernel,
                         cudaFuncAttributeMaxDynamicSharedMemorySize, 65536);
    cudaFuncSetAttribute(sweep_kernel,
                         cudaFuncAttributeMaxDynamicSharedMemorySize, MASK_BYTES);

    score_kernel<<<(BDIM * PDIM + 255) / 256, 256>>>(conf);
    select_kernel<<<NPAIR, 1024, 65536>>>(cth, loc, prior);
    mask_kernel<<<NPAIR * MCHUNK, 512>>>(nth);
    sweep_kernel<<<NPAIR, 256, MASK_BYTES>>>(out);
}